// round 4
// baseline (speedup 1.0000x reference)
#include <cuda_runtime.h>
#include <cuda_bf16.h>
#include <cstdint>

// ---------------------------------------------------------------------------
#define BATCH 64
#define SEQ   1024
#define EDIM  256
#define HDIM  256
#define MTOT  (BATCH * SEQ)       // 65536

// Pre-split bf16 operands (hi/lo), produced once, consumed by MMA mainloops.
__device__ __nv_bfloat16 g_xh [(size_t)MTOT * EDIM];
__device__ __nv_bfloat16 g_xl [(size_t)MTOT * EDIM];
__device__ __nv_bfloat16 g_qh [(size_t)MTOT * HDIM];
__device__ __nv_bfloat16 g_ql [(size_t)MTOT * HDIM];
__device__ __nv_bfloat16 g_kh [(size_t)MTOT * HDIM];
__device__ __nv_bfloat16 g_kl [(size_t)MTOT * HDIM];
__device__ __nv_bfloat16 g_vth[(size_t)BATCH * EDIM * SEQ];
__device__ __nv_bfloat16 g_vtl[(size_t)BATCH * EDIM * SEQ];
__device__ __nv_bfloat16 g_ph [(size_t)BATCH * SEQ * SEQ];
__device__ __nv_bfloat16 g_pl [(size_t)BATCH * SEQ * SEQ];
__device__ float         g_s  [(size_t)BATCH * SEQ * SEQ];   // fp32 logits
__device__ __nv_bfloat16 g_wqTh[EDIM * HDIM], g_wqTl[EDIM * HDIM];
__device__ __nv_bfloat16 g_wkTh[EDIM * HDIM], g_wkTl[EDIM * HDIM];
__device__ __nv_bfloat16 g_wvTh[EDIM * HDIM], g_wvTl[EDIM * HDIM];

// ---------------------------------------------------------------------------
// helpers
// ---------------------------------------------------------------------------
__device__ __forceinline__ uint32_t smem_u32(const void* p) {
    uint32_t a;
    asm("{ .reg .u64 t; cvta.to.shared.u64 t, %1; cvt.u32.u64 %0, t; }" : "=r"(a) : "l"(p));
    return a;
}
__device__ __forceinline__ void ldsm_x4(uint32_t* r, uint32_t addr) {
    asm volatile("ldmatrix.sync.aligned.m8n8.x4.shared.b16 {%0,%1,%2,%3}, [%4];"
                 : "=r"(r[0]), "=r"(r[1]), "=r"(r[2]), "=r"(r[3]) : "r"(addr));
}
__device__ __forceinline__ void ldsm_x2(uint32_t* r, uint32_t addr) {
    asm volatile("ldmatrix.sync.aligned.m8n8.x2.shared.b16 {%0,%1}, [%2];"
                 : "=r"(r[0]), "=r"(r[1]) : "r"(addr));
}
__device__ __forceinline__ void mma_bf16(float* c, const uint32_t* a, const uint32_t* b) {
    asm volatile(
        "mma.sync.aligned.m16n8k16.row.col.f32.bf16.bf16.f32 "
        "{%0,%1,%2,%3}, {%4,%5,%6,%7}, {%8,%9}, {%0,%1,%2,%3};"
        : "+f"(c[0]), "+f"(c[1]), "+f"(c[2]), "+f"(c[3])
        : "r"(a[0]), "r"(a[1]), "r"(a[2]), "r"(a[3]), "r"(b[0]), "r"(b[1]));
}
// hi/lo bf16 split of two floats, packed as bf16x2 words
__device__ __forceinline__ void split2(float x, float y, uint32_t& h, uint32_t& l) {
    __nv_bfloat162 H = __floats2bfloat162_rn(x, y);
    float hx = __bfloat162float(__low2bfloat16(H));
    float hy = __bfloat162float(__high2bfloat16(H));
    __nv_bfloat162 L = __floats2bfloat162_rn(x - hx, y - hy);
    h = *reinterpret_cast<uint32_t*>(&H);
    l = *reinterpret_cast<uint32_t*>(&L);
}

#define CP16(sm, gp)  asm volatile("cp.async.cg.shared.global [%0], [%1], 16;" :: "r"(sm), "l"(gp))
#define CP_COMMIT()   asm volatile("cp.async.commit_group;" ::: "memory")
#define CP_WAIT2()    asm volatile("cp.async.wait_group 2;" ::: "memory")

// ---------------------------------------------------------------------------
// GEMM: C[128 x 128] = A[128 x K] @ B[128 x K]^T, A/B pre-split bf16 hi/lo.
// K chunks of 64 bf16 elements; 3-stage cp.async pipeline.
// smem rows padded 128B -> 144B for conflict-free ldmatrix.
// ---------------------------------------------------------------------------
#define ROWB     144
#define REG_SZ   (128 * ROWB)          // 18432
#define OFF_AH   0
#define OFF_AL   (REG_SZ)
#define OFF_BH   (2 * REG_SZ)
#define OFF_BL   (3 * REG_SZ)
#define STAGE_SZ (4 * REG_SZ)          // 73728
#define SMEM_SZ  (3 * STAGE_SZ)        // 221184

enum { M_PROJQK = 0, M_PROJVT = 1, M_QK = 2, M_PV = 3 };

template<int MODE, int NCHUNK>
__global__ __launch_bounds__(256, 1)
void gemm3(const float* __restrict__ bq, const float* __restrict__ bk,
           const float* __restrict__ bv, float* __restrict__ outp)
{
    extern __shared__ __align__(128) char smem[];
    const uint32_t sbase = smem_u32(smem);
    const int t    = threadIdx.x;
    const int lane = t & 31;
    const int wid  = t >> 5;
    const int wm   = wid >> 2;        // 0..1
    const int wn   = wid & 3;         // 0..3

    // ---- operand resolution ----
    const __nv_bfloat16 *Ah, *Al, *Bh, *Bl;
    __nv_bfloat16 *Ch = nullptr, *Cl = nullptr;
    float* Cf = nullptr;
    const float* bias = nullptr;
    size_t lda, ldb, ldc;

    if (MODE == M_PROJQK) {
        int mt = blockIdx.x, nt = blockIdx.y, qk = blockIdx.z;
        Ah = g_xh + (size_t)mt * 128 * EDIM;  Al = g_xl + (size_t)mt * 128 * EDIM;  lda = EDIM;
        Bh = (qk ? g_wkTh : g_wqTh) + (size_t)nt * 128 * EDIM;
        Bl = (qk ? g_wkTl : g_wqTl) + (size_t)nt * 128 * EDIM;                      ldb = EDIM;
        size_t co = (size_t)mt * 128 * HDIM + nt * 128;
        Ch = (qk ? g_kh : g_qh) + co;  Cl = (qk ? g_kl : g_ql) + co;                ldc = HDIM;
        bias = (qk ? bk : bq) + nt * 128;
    } else if (MODE == M_PROJVT) {
        int dt = blockIdx.x, st = blockIdx.y, b = blockIdx.z;
        Ah = g_wvTh + (size_t)dt * 128 * EDIM; Al = g_wvTl + (size_t)dt * 128 * EDIM; lda = EDIM;
        size_t bo = ((size_t)b * SEQ + st * 128) * EDIM;
        Bh = g_xh + bo;  Bl = g_xl + bo;                                            ldb = EDIM;
        size_t co = (size_t)b * EDIM * SEQ + (size_t)dt * 128 * SEQ + st * 128;
        Ch = g_vth + co;  Cl = g_vtl + co;                                          ldc = SEQ;
        bias = bv + dt * 128;
    } else if (MODE == M_QK) {
        int mt = blockIdx.x, nt = blockIdx.y, b = blockIdx.z;
        size_t ao = ((size_t)b * SEQ + mt * 128) * HDIM;
        size_t bo = ((size_t)b * SEQ + nt * 128) * HDIM;
        Ah = g_qh + ao; Al = g_ql + ao;  lda = HDIM;
        Bh = g_kh + bo; Bl = g_kl + bo;  ldb = HDIM;
        Cf = g_s + (size_t)b * SEQ * SEQ + (size_t)mt * 128 * SEQ + nt * 128;       ldc = SEQ;
    } else { // M_PV
        int mt = blockIdx.x, nt = blockIdx.y, b = blockIdx.z;
        size_t ao = (size_t)b * SEQ * SEQ + (size_t)mt * 128 * SEQ;
        size_t bo = (size_t)b * EDIM * SEQ + (size_t)nt * 128 * SEQ;
        Ah = g_ph + ao;  Al = g_pl + ao;   lda = SEQ;
        Bh = g_vth + bo; Bl = g_vtl + bo;  ldb = SEQ;
        Cf = outp + ((size_t)b * SEQ + mt * 128) * EDIM + nt * 128;                 ldc = EDIM;
    }

    float acc[4][4][4];
#pragma unroll
    for (int i = 0; i < 4; i++)
#pragma unroll
        for (int j = 0; j < 4; j++)
#pragma unroll
            for (int e = 0; e < 4; e++) acc[i][j][e] = 0.f;

    // per-thread cp.async mapping: idx -> (row, 16B chunk)
    const int r_ld = t >> 3;             // rows step 32
    const int cc16 = (t & 7) * 16;       // smem byte within row
    const int cel  = (t & 7) * 8;        // gmem element offset within chunk

#define LOAD_STAGE(J, BUF)                                                     \
    {                                                                          \
        const uint32_t sp = sbase + (BUF) * STAGE_SZ;                          \
        _Pragma("unroll")                                                      \
        for (int i = 0; i < 4; i++) {                                          \
            int r = r_ld + 32 * i;                                             \
            uint32_t so = (uint32_t)(r * ROWB + cc16);                         \
            size_t ga = (size_t)r * lda + (size_t)(J) * 64 + cel;              \
            size_t gb = (size_t)r * ldb + (size_t)(J) * 64 + cel;              \
            CP16(sp + OFF_AH + so, Ah + ga);                                   \
            CP16(sp + OFF_AL + so, Al + ga);                                   \
            CP16(sp + OFF_BH + so, Bh + gb);                                   \
            CP16(sp + OFF_BL + so, Bl + gb);                                   \
        }                                                                      \
    }

    // fragment smem byte offsets (within a region)
    const uint32_t aoff = (uint32_t)((wm * 64 + (lane & 15)) * ROWB + ((lane >> 4) << 4));
    const uint32_t boff = (uint32_t)((wn * 32 + (lane & 7)) * ROWB + (((lane >> 3) & 1) << 4));

    // prologue: fill 3 stages
    LOAD_STAGE(0, 0); CP_COMMIT();
    LOAD_STAGE(1, 1); CP_COMMIT();
    LOAD_STAGE(2, 2); CP_COMMIT();

    int buf = 0;
#pragma unroll 1
    for (int j = 0; j < NCHUNK; j++) {
        CP_WAIT2();
        __syncthreads();

        const uint32_t st = sbase + (uint32_t)(buf * STAGE_SZ);
#pragma unroll
        for (int ks = 0; ks < 4; ks++) {
            const uint32_t ko = (uint32_t)(ks * 32);
            uint32_t ah[4][4], al[4][4], bh[4][2], bl[4][2];
#pragma unroll
            for (int mf = 0; mf < 4; mf++) {
                uint32_t a = st + aoff + (uint32_t)(mf * 16 * ROWB) + ko;
                ldsm_x4(ah[mf], a + OFF_AH);
                ldsm_x4(al[mf], a + OFF_AL);
            }
#pragma unroll
            for (int nf = 0; nf < 4; nf++) {
                uint32_t b = st + boff + (uint32_t)(nf * 8 * ROWB) + ko;
                ldsm_x2(bh[nf], b + OFF_BH);
                ldsm_x2(bl[nf], b + OFF_BL);
            }
#pragma unroll
            for (int mf = 0; mf < 4; mf++)
#pragma unroll
                for (int nf = 0; nf < 4; nf++) mma_bf16(acc[mf][nf], ah[mf], bh[nf]);
#pragma unroll
            for (int mf = 0; mf < 4; mf++)
#pragma unroll
                for (int nf = 0; nf < 4; nf++) mma_bf16(acc[mf][nf], ah[mf], bl[nf]);
#pragma unroll
            for (int mf = 0; mf < 4; mf++)
#pragma unroll
                for (int nf = 0; nf < 4; nf++) mma_bf16(acc[mf][nf], al[mf], bh[nf]);
        }
        __syncthreads();

        if (j + 3 < NCHUNK) LOAD_STAGE(j + 3, buf);
        CP_COMMIT();   // commit (possibly empty) keeps group count stable
        buf = (buf == 2) ? 0 : buf + 1;
    }

    // ---- epilogue ----
#pragma unroll
    for (int mf = 0; mf < 4; mf++) {
        const int r0 = wm * 64 + mf * 16 + (lane >> 2);
        const int r1 = r0 + 8;
#pragma unroll
        for (int nf = 0; nf < 4; nf++) {
            const int c = wn * 32 + nf * 8 + ((lane & 3) << 1);
            float* a = acc[mf][nf];
            if (MODE == M_PROJQK) {
                float cb0 = bias[c], cb1 = bias[c + 1];
                uint32_t h, l;
                split2(a[0] + cb0, a[1] + cb1, h, l);
                *(uint32_t*)(Ch + (size_t)r0 * ldc + c) = h;
                *(uint32_t*)(Cl + (size_t)r0 * ldc + c) = l;
                split2(a[2] + cb0, a[3] + cb1, h, l);
                *(uint32_t*)(Ch + (size_t)r1 * ldc + c) = h;
                *(uint32_t*)(Cl + (size_t)r1 * ldc + c) = l;
            } else if (MODE == M_PROJVT) {
                float rb0 = bias[r0], rb1 = bias[r1];
                uint32_t h, l;
                split2(a[0] + rb0, a[1] + rb0, h, l);
                *(uint32_t*)(Ch + (size_t)r0 * ldc + c) = h;
                *(uint32_t*)(Cl + (size_t)r0 * ldc + c) = l;
                split2(a[2] + rb1, a[3] + rb1, h, l);
                *(uint32_t*)(Ch + (size_t)r1 * ldc + c) = h;
                *(uint32_t*)(Cl + (size_t)r1 * ldc + c) = l;
            } else {
                *(float2*)(Cf + (size_t)r0 * ldc + c) = make_float2(a[0], a[1]);
                *(float2*)(Cf + (size_t)r1 * ldc + c) = make_float2(a[2], a[3]);
            }
        }
    }
#undef LOAD_STAGE
}

// ---------------------------------------------------------------------------
// Prep: split x into bf16 hi/lo
// ---------------------------------------------------------------------------
__global__ __launch_bounds__(256) void split_x(const float* __restrict__ x)
{
    size_t i = ((size_t)blockIdx.x * 256 + threadIdx.x) * 4;
    float4 v = *(const float4*)(x + i);
    uint32_t h01, l01, h23, l23;
    split2(v.x, v.y, h01, l01);
    split2(v.z, v.w, h23, l23);
    *(uint2*)(g_xh + i) = make_uint2(h01, h23);
    *(uint2*)(g_xl + i) = make_uint2(l01, l23);
}

// ---------------------------------------------------------------------------
// Prep: transpose W and split into bf16 hi/lo
// ---------------------------------------------------------------------------
__global__ __launch_bounds__(256) void transpose_split_w(const float* __restrict__ Wq,
                                                         const float* __restrict__ Wk,
                                                         const float* __restrict__ Wv)
{
    const float* src = (blockIdx.x == 0) ? Wq : (blockIdx.x == 1) ? Wk : Wv;
    __nv_bfloat16* dh = (blockIdx.x == 0) ? g_wqTh : (blockIdx.x == 1) ? g_wkTh : g_wvTh;
    __nv_bfloat16* dl = (blockIdx.x == 0) ? g_wqTl : (blockIdx.x == 1) ? g_wkTl : g_wvTl;
    __shared__ float sm[32 * 33];
    int w = threadIdx.x >> 5, l = threadIdx.x & 31;
    for (int ti = 0; ti < 8; ti++)
        for (int tj = 0; tj < 8; tj++) {
#pragma unroll
            for (int k = 0; k < 4; k++) {
                int r = w * 4 + k;
                sm[r * 33 + l] = src[(size_t)(ti * 32 + r) * 256 + tj * 32 + l];
            }
            __syncthreads();
#pragma unroll
            for (int k = 0; k < 4; k++) {
                int r = w * 4 + k;
                float v = sm[l * 33 + r];
                __nv_bfloat16 h = __float2bfloat16_rn(v);
                float hv = __bfloat162float(h);
                dh[(size_t)(tj * 32 + r) * 256 + ti * 32 + l] = h;
                dl[(size_t)(tj * 32 + r) * 256 + ti * 32 + l] = __float2bfloat16_rn(v - hv);
            }
            __syncthreads();
        }
}

// ---------------------------------------------------------------------------
// Softmax: one warp per row; reads fp32 logits, writes P as bf16 hi/lo
// ---------------------------------------------------------------------------
__global__ __launch_bounds__(256) void softmax_rows()
{
    const size_t row = (size_t)blockIdx.x * 8 + (threadIdx.x >> 5);
    const int l = threadIdx.x & 31;
    const float4* p = (const float4*)(g_s + row * SEQ);

    float4 v[8];
    float mx = -3.4e38f;
#pragma unroll
    for (int i = 0; i < 8; i++) {
        v[i] = p[i * 32 + l];
        mx = fmaxf(mx, fmaxf(fmaxf(v[i].x, v[i].y), fmaxf(v[i].z, v[i].w)));
    }
#pragma unroll
    for (int o = 16; o > 0; o >>= 1) mx = fmaxf(mx, __shfl_xor_sync(0xffffffffu, mx, o));

    float sum = 0.f;
#pragma unroll
    for (int i = 0; i < 8; i++) {
        v[i].x = __expf(v[i].x - mx); v[i].y = __expf(v[i].y - mx);
        v[i].z = __expf(v[i].z - mx); v[i].w = __expf(v[i].w - mx);
        sum += (v[i].x + v[i].y) + (v[i].z + v[i].w);
    }
#pragma unroll
    for (int o = 16; o > 0; o >>= 1) sum += __shfl_xor_sync(0xffffffffu, sum, o);

    const float inv = 1.f / sum;
    __nv_bfloat16* ph = g_ph + row * SEQ;
    __nv_bfloat16* pl = g_pl + row * SEQ;
#pragma unroll
    for (int i = 0; i < 8; i++) {
        uint32_t h01, l01, h23, l23;
        split2(v[i].x * inv, v[i].y * inv, h01, l01);
        split2(v[i].z * inv, v[i].w * inv, h23, l23);
        size_t off = (size_t)(i * 32 + l) * 4;
        *(uint2*)(ph + off) = make_uint2(h01, h23);
        *(uint2*)(pl + off) = make_uint2(l01, l23);
    }
}

// ---------------------------------------------------------------------------
extern "C" void kernel_launch(void* const* d_in, const int* in_sizes, int n_in,
                              void* d_out, int out_size)
{
    const float* x  = (const float*)d_in[0];
    const float* Wq = (const float*)d_in[1];
    const float* bq = (const float*)d_in[2];
    const float* Wk = (const float*)d_in[3];
    const float* bk = (const float*)d_in[4];
    const float* Wv = (const float*)d_in[5];
    const float* bv = (const float*)d_in[6];
    float* out = (float*)d_out;

    cudaFuncSetAttribute(gemm3<M_PROJQK, 4>, cudaFuncAttributeMaxDynamicSharedMemorySize, SMEM_SZ);
    cudaFuncSetAttribute(gemm3<M_PROJVT, 4>, cudaFuncAttributeMaxDynamicSharedMemorySize, SMEM_SZ);
    cudaFuncSetAttribute(gemm3<M_QK, 4>,     cudaFuncAttributeMaxDynamicSharedMemorySize, SMEM_SZ);
    cudaFuncSetAttribute(gemm3<M_PV, 16>,    cudaFuncAttributeMaxDynamicSharedMemorySize, SMEM_SZ);

    split_x<<<(MTOT * EDIM) / 1024, 256>>>(x);
    transpose_split_w<<<3, 256>>>(Wq, Wk, Wv);

    gemm3<M_PROJQK, 4><<<dim3(MTOT / 128, 2, 2), 256, SMEM_SZ>>>(bq, bk, bv, out);
    gemm3<M_PROJVT, 4><<<dim3(2, 8, BATCH),      256, SMEM_SZ>>>(bq, bk, bv, out);
    gemm3<M_QK, 4>    <<<dim3(8, 8, BATCH),      256, SMEM_SZ>>>(bq, bk, bv, out);
    softmax_rows      <<<MTOT / 8, 256>>>();
    gemm3<M_PV, 16>   <<<dim3(8, 2, BATCH),      256, SMEM_SZ>>>(bq, bk, bv, out);
}

// round 5
// speedup vs baseline: 1.0171x; 1.0171x over previous
#include <cuda_runtime.h>
#include <cuda_bf16.h>
#include <cstdint>

// ---------------------------------------------------------------------------
#define BATCH 64
#define SEQ   1024
#define EDIM  256
#define HDIM  256
#define MTOT  (BATCH * SEQ)       // 65536

// Pre-split bf16 operands (hi/lo), produced once, consumed by MMA mainloops.
__device__ __nv_bfloat16 g_xh [(size_t)MTOT * EDIM];
__device__ __nv_bfloat16 g_xl [(size_t)MTOT * EDIM];
__device__ __nv_bfloat16 g_qh [(size_t)MTOT * HDIM];
__device__ __nv_bfloat16 g_ql [(size_t)MTOT * HDIM];
__device__ __nv_bfloat16 g_kh [(size_t)MTOT * HDIM];
__device__ __nv_bfloat16 g_kl [(size_t)MTOT * HDIM];
__device__ __nv_bfloat16 g_vth[(size_t)BATCH * EDIM * SEQ];
__device__ __nv_bfloat16 g_vtl[(size_t)BATCH * EDIM * SEQ];
__device__ __nv_bfloat16 g_ph [(size_t)BATCH * SEQ * SEQ];
__device__ __nv_bfloat16 g_pl [(size_t)BATCH * SEQ * SEQ];
__device__ float         g_s  [(size_t)BATCH * SEQ * SEQ];   // fp32 logits
__device__ __nv_bfloat16 g_wqTh[EDIM * HDIM], g_wqTl[EDIM * HDIM];
__device__ __nv_bfloat16 g_wkTh[EDIM * HDIM], g_wkTl[EDIM * HDIM];
__device__ __nv_bfloat16 g_wvTh[EDIM * HDIM], g_wvTl[EDIM * HDIM];

// ---------------------------------------------------------------------------
// helpers
// ---------------------------------------------------------------------------
__device__ __forceinline__ uint32_t smem_u32(const void* p) {
    uint32_t a;
    asm("{ .reg .u64 t; cvta.to.shared.u64 t, %1; cvt.u32.u64 %0, t; }" : "=r"(a) : "l"(p));
    return a;
}
__device__ __forceinline__ void ldsm_x4(uint32_t* r, uint32_t addr) {
    asm volatile("ldmatrix.sync.aligned.m8n8.x4.shared.b16 {%0,%1,%2,%3}, [%4];"
                 : "=r"(r[0]), "=r"(r[1]), "=r"(r[2]), "=r"(r[3]) : "r"(addr));
}
__device__ __forceinline__ void ldsm_x2(uint32_t* r, uint32_t addr) {
    asm volatile("ldmatrix.sync.aligned.m8n8.x2.shared.b16 {%0,%1}, [%2];"
                 : "=r"(r[0]), "=r"(r[1]) : "r"(addr));
}
__device__ __forceinline__ void mma_bf16(float* c, const uint32_t* a, const uint32_t* b) {
    asm volatile(
        "mma.sync.aligned.m16n8k16.row.col.f32.bf16.bf16.f32 "
        "{%0,%1,%2,%3}, {%4,%5,%6,%7}, {%8,%9}, {%0,%1,%2,%3};"
        : "+f"(c[0]), "+f"(c[1]), "+f"(c[2]), "+f"(c[3])
        : "r"(a[0]), "r"(a[1]), "r"(a[2]), "r"(a[3]), "r"(b[0]), "r"(b[1]));
}
// hi/lo bf16 split of two floats, packed as bf16x2 words
__device__ __forceinline__ void split2(float x, float y, uint32_t& h, uint32_t& l) {
    __nv_bfloat162 H = __floats2bfloat162_rn(x, y);
    float hx = __bfloat162float(__low2bfloat16(H));
    float hy = __bfloat162float(__high2bfloat16(H));
    __nv_bfloat162 L = __floats2bfloat162_rn(x - hx, y - hy);
    h = *reinterpret_cast<uint32_t*>(&H);
    l = *reinterpret_cast<uint32_t*>(&L);
}

#define CP16(sm, gp)  asm volatile("cp.async.cg.shared.global [%0], [%1], 16;" :: "r"(sm), "l"(gp))
#define CP_COMMIT()   asm volatile("cp.async.commit_group;" ::: "memory")
#define CP_WAIT1()    asm volatile("cp.async.wait_group 1;" ::: "memory")

// ---------------------------------------------------------------------------
// GEMM: C[128 x 128] = A[128 x K] @ B[128 x K]^T, A/B pre-split bf16 hi/lo.
// K chunks of 32 elements (64B rows, padded to 80B); 2-stage cp.async pipe;
// smem 80KB/CTA -> 2 CTAs/SM (16 warps/SM).
// ---------------------------------------------------------------------------
#define ROWB     80
#define REG_SZ   (128 * ROWB)          // 10240
#define OFF_AH   0
#define OFF_AL   (REG_SZ)
#define OFF_BH   (2 * REG_SZ)
#define OFF_BL   (3 * REG_SZ)
#define STAGE_SZ (4 * REG_SZ)          // 40960
#define SMEM_SZ  (2 * STAGE_SZ)        // 81920

enum { M_PROJQK = 0, M_PROJVT = 1, M_QK = 2, M_PV = 3 };

template<int MODE, int NCHUNK>
__global__ __launch_bounds__(256, 2)
void gemm3(const float* __restrict__ bq, const float* __restrict__ bk,
           const float* __restrict__ bv, float* __restrict__ outp)
{
    extern __shared__ __align__(128) char smem[];
    const uint32_t sbase = smem_u32(smem);
    const int t    = threadIdx.x;
    const int lane = t & 31;
    const int wid  = t >> 5;
    const int wm   = wid >> 2;        // 0..1
    const int wn   = wid & 3;         // 0..3

    // ---- operand resolution ----
    const __nv_bfloat16 *Ah, *Al, *Bh, *Bl;
    __nv_bfloat16 *Ch = nullptr, *Cl = nullptr;
    float* Cf = nullptr;
    const float* bias = nullptr;
    size_t lda, ldb, ldc;

    if (MODE == M_PROJQK) {
        int mt = blockIdx.x, nt = blockIdx.y, qk = blockIdx.z;
        Ah = g_xh + (size_t)mt * 128 * EDIM;  Al = g_xl + (size_t)mt * 128 * EDIM;  lda = EDIM;
        Bh = (qk ? g_wkTh : g_wqTh) + (size_t)nt * 128 * EDIM;
        Bl = (qk ? g_wkTl : g_wqTl) + (size_t)nt * 128 * EDIM;                      ldb = EDIM;
        size_t co = (size_t)mt * 128 * HDIM + nt * 128;
        Ch = (qk ? g_kh : g_qh) + co;  Cl = (qk ? g_kl : g_ql) + co;                ldc = HDIM;
        bias = (qk ? bk : bq) + nt * 128;
    } else if (MODE == M_PROJVT) {
        int dt = blockIdx.x, st = blockIdx.y, b = blockIdx.z;
        Ah = g_wvTh + (size_t)dt * 128 * EDIM; Al = g_wvTl + (size_t)dt * 128 * EDIM; lda = EDIM;
        size_t bo = ((size_t)b * SEQ + st * 128) * EDIM;
        Bh = g_xh + bo;  Bl = g_xl + bo;                                            ldb = EDIM;
        size_t co = (size_t)b * EDIM * SEQ + (size_t)dt * 128 * SEQ + st * 128;
        Ch = g_vth + co;  Cl = g_vtl + co;                                          ldc = SEQ;
        bias = bv + dt * 128;
    } else if (MODE == M_QK) {
        int mt = blockIdx.x, nt = blockIdx.y, b = blockIdx.z;
        size_t ao = ((size_t)b * SEQ + mt * 128) * HDIM;
        size_t bo = ((size_t)b * SEQ + nt * 128) * HDIM;
        Ah = g_qh + ao; Al = g_ql + ao;  lda = HDIM;
        Bh = g_kh + bo; Bl = g_kl + bo;  ldb = HDIM;
        Cf = g_s + (size_t)b * SEQ * SEQ + (size_t)mt * 128 * SEQ + nt * 128;       ldc = SEQ;
    } else { // M_PV
        int mt = blockIdx.x, nt = blockIdx.y, b = blockIdx.z;
        size_t ao = (size_t)b * SEQ * SEQ + (size_t)mt * 128 * SEQ;
        size_t bo = (size_t)b * EDIM * SEQ + (size_t)nt * 128 * SEQ;
        Ah = g_ph + ao;  Al = g_pl + ao;   lda = SEQ;
        Bh = g_vth + bo; Bl = g_vtl + bo;  ldb = SEQ;
        Cf = outp + ((size_t)b * SEQ + mt * 128) * EDIM + nt * 128;                 ldc = EDIM;
    }

    float acc[4][4][4];
#pragma unroll
    for (int i = 0; i < 4; i++)
#pragma unroll
        for (int j = 0; j < 4; j++)
#pragma unroll
            for (int e = 0; e < 4; e++) acc[i][j][e] = 0.f;

    // cp.async mapping: 128 rows x 64B per region, 16B per txn.
    // thread t -> rows {t>>2, t>>2 + 64}, byte chunk (t&3)*16
    const int r_ld = t >> 2;             // 0..63
    const int cb16 = (t & 3) * 16;       // smem byte within row
    const int cel  = (t & 3) * 8;        // gmem element offset within chunk

#define LOAD_STAGE(J, BUF)                                                     \
    {                                                                          \
        const uint32_t sp = sbase + (BUF) * STAGE_SZ;                          \
        _Pragma("unroll")                                                      \
        for (int i = 0; i < 2; i++) {                                          \
            int r = r_ld + 64 * i;                                             \
            uint32_t so = (uint32_t)(r * ROWB + cb16);                         \
            size_t ga = (size_t)r * lda + (size_t)(J) * 32 + cel;              \
            size_t gb = (size_t)r * ldb + (size_t)(J) * 32 + cel;              \
            CP16(sp + OFF_AH + so, Ah + ga);                                   \
            CP16(sp + OFF_AL + so, Al + ga);                                   \
            CP16(sp + OFF_BH + so, Bh + gb);                                   \
            CP16(sp + OFF_BL + so, Bl + gb);                                   \
        }                                                                      \
    }

    // fragment smem byte offsets (within a region)
    const uint32_t aoff = (uint32_t)((wm * 64 + (lane & 15)) * ROWB + ((lane >> 4) << 4));
    const uint32_t boff = (uint32_t)((wn * 32 + (lane & 7)) * ROWB + (((lane >> 3) & 1) << 4));

    // prologue: fill both stages
    LOAD_STAGE(0, 0); CP_COMMIT();
    LOAD_STAGE(1, 1); CP_COMMIT();

#pragma unroll 1
    for (int j = 0; j < NCHUNK; j++) {
        CP_WAIT1();
        __syncthreads();

        const uint32_t st = sbase + (uint32_t)((j & 1) * STAGE_SZ);
#pragma unroll
        for (int ks = 0; ks < 2; ks++) {
            const uint32_t ko = (uint32_t)(ks * 32);
            uint32_t ah[4][4], al[4][4], b2[4][2];
#pragma unroll
            for (int mf = 0; mf < 4; mf++) {
                uint32_t a = st + aoff + (uint32_t)(mf * 16 * ROWB) + ko;
                ldsm_x4(ah[mf], a + OFF_AH);
            }
#pragma unroll
            for (int nf = 0; nf < 4; nf++)
                ldsm_x2(b2[nf], st + boff + (uint32_t)(nf * 8 * ROWB) + ko + OFF_BH);
#pragma unroll
            for (int mf = 0; mf < 4; mf++)
#pragma unroll
                for (int nf = 0; nf < 4; nf++) mma_bf16(acc[mf][nf], ah[mf], b2[nf]);
            // lo(A) x hi(B)
#pragma unroll
            for (int mf = 0; mf < 4; mf++) {
                uint32_t a = st + aoff + (uint32_t)(mf * 16 * ROWB) + ko;
                ldsm_x4(al[mf], a + OFF_AL);
            }
#pragma unroll
            for (int mf = 0; mf < 4; mf++)
#pragma unroll
                for (int nf = 0; nf < 4; nf++) mma_bf16(acc[mf][nf], al[mf], b2[nf]);
            // hi(A) x lo(B)  (reuse b2 registers)
#pragma unroll
            for (int nf = 0; nf < 4; nf++)
                ldsm_x2(b2[nf], st + boff + (uint32_t)(nf * 8 * ROWB) + ko + OFF_BL);
#pragma unroll
            for (int mf = 0; mf < 4; mf++)
#pragma unroll
                for (int nf = 0; nf < 4; nf++) mma_bf16(acc[mf][nf], ah[mf], b2[nf]);
        }
        __syncthreads();

        if (j + 2 < NCHUNK) LOAD_STAGE(j + 2, j & 1);
        CP_COMMIT();   // unconditional: keeps group accounting uniform
    }

    // ---- epilogue ----
#pragma unroll
    for (int mf = 0; mf < 4; mf++) {
        const int r0 = wm * 64 + mf * 16 + (lane >> 2);
        const int r1 = r0 + 8;
#pragma unroll
        for (int nf = 0; nf < 4; nf++) {
            const int c = wn * 32 + nf * 8 + ((lane & 3) << 1);
            float* a = acc[mf][nf];
            if (MODE == M_PROJQK) {
                float cb0 = bias[c], cb1 = bias[c + 1];
                uint32_t h, l;
                split2(a[0] + cb0, a[1] + cb1, h, l);
                *(uint32_t*)(Ch + (size_t)r0 * ldc + c) = h;
                *(uint32_t*)(Cl + (size_t)r0 * ldc + c) = l;
                split2(a[2] + cb0, a[3] + cb1, h, l);
                *(uint32_t*)(Ch + (size_t)r1 * ldc + c) = h;
                *(uint32_t*)(Cl + (size_t)r1 * ldc + c) = l;
            } else if (MODE == M_PROJVT) {
                float rb0 = bias[r0], rb1 = bias[r1];
                uint32_t h, l;
                split2(a[0] + rb0, a[1] + rb0, h, l);
                *(uint32_t*)(Ch + (size_t)r0 * ldc + c) = h;
                *(uint32_t*)(Cl + (size_t)r0 * ldc + c) = l;
                split2(a[2] + rb1, a[3] + rb1, h, l);
                *(uint32_t*)(Ch + (size_t)r1 * ldc + c) = h;
                *(uint32_t*)(Cl + (size_t)r1 * ldc + c) = l;
            } else {
                *(float2*)(Cf + (size_t)r0 * ldc + c) = make_float2(a[0], a[1]);
                *(float2*)(Cf + (size_t)r1 * ldc + c) = make_float2(a[2], a[3]);
            }
        }
    }
#undef LOAD_STAGE
}

// ---------------------------------------------------------------------------
// Prep: split x into bf16 hi/lo
// ---------------------------------------------------------------------------
__global__ __launch_bounds__(256) void split_x(const float* __restrict__ x)
{
    size_t i = ((size_t)blockIdx.x * 256 + threadIdx.x) * 4;
    float4 v = *(const float4*)(x + i);
    uint32_t h01, l01, h23, l23;
    split2(v.x, v.y, h01, l01);
    split2(v.z, v.w, h23, l23);
    *(uint2*)(g_xh + i) = make_uint2(h01, h23);
    *(uint2*)(g_xl + i) = make_uint2(l01, l23);
}

// ---------------------------------------------------------------------------
// Prep: transpose W and split into bf16 hi/lo
// ---------------------------------------------------------------------------
__global__ __launch_bounds__(256) void transpose_split_w(const float* __restrict__ Wq,
                                                         const float* __restrict__ Wk,
                                                         const float* __restrict__ Wv)
{
    const float* src = (blockIdx.x == 0) ? Wq : (blockIdx.x == 1) ? Wk : Wv;
    __nv_bfloat16* dh = (blockIdx.x == 0) ? g_wqTh : (blockIdx.x == 1) ? g_wkTh : g_wvTh;
    __nv_bfloat16* dl = (blockIdx.x == 0) ? g_wqTl : (blockIdx.x == 1) ? g_wkTl : g_wvTl;
    __shared__ float sm[32 * 33];
    int w = threadIdx.x >> 5, l = threadIdx.x & 31;
    for (int ti = 0; ti < 8; ti++)
        for (int tj = 0; tj < 8; tj++) {
#pragma unroll
            for (int k = 0; k < 4; k++) {
                int r = w * 4 + k;
                sm[r * 33 + l] = src[(size_t)(ti * 32 + r) * 256 + tj * 32 + l];
            }
            __syncthreads();
#pragma unroll
            for (int k = 0; k < 4; k++) {
                int r = w * 4 + k;
                float v = sm[l * 33 + r];
                __nv_bfloat16 h = __float2bfloat16_rn(v);
                float hv = __bfloat162float(h);
                dh[(size_t)(tj * 32 + r) * 256 + ti * 32 + l] = h;
                dl[(size_t)(tj * 32 + r) * 256 + ti * 32 + l] = __float2bfloat16_rn(v - hv);
            }
            __syncthreads();
        }
}

// ---------------------------------------------------------------------------
// Softmax: one warp per row; reads fp32 logits, writes P as bf16 hi/lo
// ---------------------------------------------------------------------------
__global__ __launch_bounds__(256) void softmax_rows()
{
    const size_t row = (size_t)blockIdx.x * 8 + (threadIdx.x >> 5);
    const int l = threadIdx.x & 31;
    const float4* p = (const float4*)(g_s + row * SEQ);

    float4 v[8];
    float mx = -3.4e38f;
#pragma unroll
    for (int i = 0; i < 8; i++) {
        v[i] = p[i * 32 + l];
        mx = fmaxf(mx, fmaxf(fmaxf(v[i].x, v[i].y), fmaxf(v[i].z, v[i].w)));
    }
#pragma unroll
    for (int o = 16; o > 0; o >>= 1) mx = fmaxf(mx, __shfl_xor_sync(0xffffffffu, mx, o));

    float sum = 0.f;
#pragma unroll
    for (int i = 0; i < 8; i++) {
        v[i].x = __expf(v[i].x - mx); v[i].y = __expf(v[i].y - mx);
        v[i].z = __expf(v[i].z - mx); v[i].w = __expf(v[i].w - mx);
        sum += (v[i].x + v[i].y) + (v[i].z + v[i].w);
    }
#pragma unroll
    for (int o = 16; o > 0; o >>= 1) sum += __shfl_xor_sync(0xffffffffu, sum, o);

    const float inv = 1.f / sum;
    __nv_bfloat16* ph = g_ph + row * SEQ;
    __nv_bfloat16* pl = g_pl + row * SEQ;
#pragma unroll
    for (int i = 0; i < 8; i++) {
        uint32_t h01, l01, h23, l23;
        split2(v[i].x * inv, v[i].y * inv, h01, l01);
        split2(v[i].z * inv, v[i].w * inv, h23, l23);
        size_t off = (size_t)(i * 32 + l) * 4;
        *(uint2*)(ph + off) = make_uint2(h01, h23);
        *(uint2*)(pl + off) = make_uint2(l01, l23);
    }
}

// ---------------------------------------------------------------------------
extern "C" void kernel_launch(void* const* d_in, const int* in_sizes, int n_in,
                              void* d_out, int out_size)
{
    const float* x  = (const float*)d_in[0];
    const float* Wq = (const float*)d_in[1];
    const float* bq = (const float*)d_in[2];
    const float* Wk = (const float*)d_in[3];
    const float* bk = (const float*)d_in[4];
    const float* Wv = (const float*)d_in[5];
    const float* bv = (const float*)d_in[6];
    float* out = (float*)d_out;

    cudaFuncSetAttribute(gemm3<M_PROJQK, 8>,  cudaFuncAttributeMaxDynamicSharedMemorySize, SMEM_SZ);
    cudaFuncSetAttribute(gemm3<M_PROJVT, 8>,  cudaFuncAttributeMaxDynamicSharedMemorySize, SMEM_SZ);
    cudaFuncSetAttribute(gemm3<M_QK, 8>,      cudaFuncAttributeMaxDynamicSharedMemorySize, SMEM_SZ);
    cudaFuncSetAttribute(gemm3<M_PV, 32>,     cudaFuncAttributeMaxDynamicSharedMemorySize, SMEM_SZ);

    split_x<<<(MTOT * EDIM) / 1024, 256>>>(x);
    transpose_split_w<<<3, 256>>>(Wq, Wk, Wv);

    gemm3<M_PROJQK, 8><<<dim3(MTOT / 128, 2, 2), 256, SMEM_SZ>>>(bq, bk, bv, out);
    gemm3<M_PROJVT, 8><<<dim3(2, 8, BATCH),      256, SMEM_SZ>>>(bq, bk, bv, out);
    gemm3<M_QK, 8>    <<<dim3(8, 8, BATCH),      256, SMEM_SZ>>>(bq, bk, bv, out);
    softmax_rows      <<<MTOT / 8, 256>>>();
    gemm3<M_PV, 32>   <<<dim3(8, 2, BATCH),      256, SMEM_SZ>>>(bq, bk, bv, out);
}

// round 6
// speedup vs baseline: 1.0789x; 1.0607x over previous
#include <cuda_runtime.h>
#include <cuda_bf16.h>
#include <cstdint>

// ---------------------------------------------------------------------------
#define BATCH 64
#define SEQ   1024
#define EDIM  256
#define HDIM  256
#define MTOT  (BATCH * SEQ)       // 65536

// Pre-split bf16 operands (hi/lo), produced once, consumed by MMA mainloops.
__device__ __nv_bfloat16 g_xh [(size_t)MTOT * EDIM];
__device__ __nv_bfloat16 g_xl [(size_t)MTOT * EDIM];
__device__ __nv_bfloat16 g_qh [(size_t)MTOT * HDIM];
__device__ __nv_bfloat16 g_ql [(size_t)MTOT * HDIM];
__device__ __nv_bfloat16 g_kh [(size_t)MTOT * HDIM];
__device__ __nv_bfloat16 g_kl [(size_t)MTOT * HDIM];
__device__ __nv_bfloat16 g_vth[(size_t)BATCH * EDIM * SEQ];
__device__ __nv_bfloat16 g_vtl[(size_t)BATCH * EDIM * SEQ];
__device__ __nv_bfloat16 g_ph [(size_t)BATCH * SEQ * SEQ];
__device__ __nv_bfloat16 g_pl [(size_t)BATCH * SEQ * SEQ];
__device__ float         g_s  [(size_t)BATCH * SEQ * SEQ];   // fp32 logits
__device__ __nv_bfloat16 g_wqTh[EDIM * HDIM], g_wqTl[EDIM * HDIM];
__device__ __nv_bfloat16 g_wkTh[EDIM * HDIM], g_wkTl[EDIM * HDIM];
__device__ __nv_bfloat16 g_wvTh[EDIM * HDIM], g_wvTl[EDIM * HDIM];

// ---------------------------------------------------------------------------
// helpers
// ---------------------------------------------------------------------------
__device__ __forceinline__ uint32_t smem_u32(const void* p) {
    uint32_t a;
    asm("{ .reg .u64 t; cvta.to.shared.u64 t, %1; cvt.u32.u64 %0, t; }" : "=r"(a) : "l"(p));
    return a;
}
__device__ __forceinline__ void ldsm_x4(uint32_t* r, uint32_t addr) {
    asm volatile("ldmatrix.sync.aligned.m8n8.x4.shared.b16 {%0,%1,%2,%3}, [%4];"
                 : "=r"(r[0]), "=r"(r[1]), "=r"(r[2]), "=r"(r[3]) : "r"(addr));
}
__device__ __forceinline__ void mma_bf16(float* c, const uint32_t* a, const uint32_t* b) {
    asm volatile(
        "mma.sync.aligned.m16n8k16.row.col.f32.bf16.bf16.f32 "
        "{%0,%1,%2,%3}, {%4,%5,%6,%7}, {%8,%9}, {%0,%1,%2,%3};"
        : "+f"(c[0]), "+f"(c[1]), "+f"(c[2]), "+f"(c[3])
        : "r"(a[0]), "r"(a[1]), "r"(a[2]), "r"(a[3]), "r"(b[0]), "r"(b[1]));
}
// hi/lo bf16 split of two floats, packed as bf16x2 words
__device__ __forceinline__ void split2(float x, float y, uint32_t& h, uint32_t& l) {
    __nv_bfloat162 H = __floats2bfloat162_rn(x, y);
    float hx = __bfloat162float(__low2bfloat16(H));
    float hy = __bfloat162float(__high2bfloat16(H));
    __nv_bfloat162 L = __floats2bfloat162_rn(x - hx, y - hy);
    h = *reinterpret_cast<uint32_t*>(&H);
    l = *reinterpret_cast<uint32_t*>(&L);
}

#define CP16(sm, gp)  asm volatile("cp.async.cg.shared.global [%0], [%1], 16;" :: "r"(sm), "l"(gp))
#define CP_COMMIT()   asm volatile("cp.async.commit_group;" ::: "memory")
#define CP_WAIT1()    asm volatile("cp.async.wait_group 1;" ::: "memory")

// ---------------------------------------------------------------------------
// GEMM: C[128 x 256] = A[128 x K] @ B[256 x K]^T, operands pre-split bf16.
// 512 threads, 16 warps (4m x 4n), warp tile 32x64.
// K in chunks of 32; 3-stage cp.async pipeline, ONE __syncthreads per chunk.
// smem rows 64B padded to 80B (conflict-free ldmatrix). 180KB -> 1 CTA/SM.
// ---------------------------------------------------------------------------
#define ROWB   80
#define S_AH   0
#define S_AL   10240                 // 128*80
#define S_BH   20480
#define S_BL   40960                 // + 256*80
#define STAGE_SZ 61440
#define SMEM_SZ  (3 * STAGE_SZ)      // 184320

enum { M_PROJQK = 0, M_PROJVT = 1, M_QK = 2, M_PV = 3 };

template<int MODE, int NCHUNK>
__global__ __launch_bounds__(512, 1)
void gemm3(const float* __restrict__ bq, const float* __restrict__ bk,
           const float* __restrict__ bv, float* __restrict__ outp)
{
    extern __shared__ __align__(128) char smem[];
    const uint32_t sbase = smem_u32(smem);
    const int t    = threadIdx.x;
    const int lane = t & 31;
    const int wid  = t >> 5;          // 0..15
    const int wm   = wid >> 2;        // 0..3  (32-row slab)
    const int wn   = wid & 3;         // 0..3  (64-col slab)

    // ---- operand resolution ----
    const __nv_bfloat16 *Ah, *Al, *Bh, *Bl;
    __nv_bfloat16 *Ch = nullptr, *Cl = nullptr;
    float* Cf = nullptr;
    const float* bias = nullptr;
    size_t lda, ldb, ldc;

    if (MODE == M_PROJQK) {
        int mt = blockIdx.x, qk = blockIdx.y;
        Ah = g_xh + (size_t)mt * 128 * EDIM;  Al = g_xl + (size_t)mt * 128 * EDIM;  lda = EDIM;
        Bh = qk ? g_wkTh : g_wqTh;  Bl = qk ? g_wkTl : g_wqTl;                      ldb = EDIM;
        size_t co = (size_t)mt * 128 * HDIM;
        Ch = (qk ? g_kh : g_qh) + co;  Cl = (qk ? g_kl : g_ql) + co;                ldc = HDIM;
        bias = qk ? bk : bq;
    } else if (MODE == M_PROJVT) {
        int mt = blockIdx.x, nt = blockIdx.y, b = blockIdx.z;
        Ah = g_wvTh + (size_t)mt * 128 * EDIM; Al = g_wvTl + (size_t)mt * 128 * EDIM; lda = EDIM;
        size_t bo = ((size_t)b * SEQ + nt * 256) * EDIM;
        Bh = g_xh + bo;  Bl = g_xl + bo;                                            ldb = EDIM;
        size_t co = (size_t)b * EDIM * SEQ + (size_t)mt * 128 * SEQ + nt * 256;
        Ch = g_vth + co;  Cl = g_vtl + co;                                          ldc = SEQ;
        bias = bv + mt * 128;
    } else if (MODE == M_QK) {
        int mt = blockIdx.x, nt = blockIdx.y, b = blockIdx.z;
        size_t ao = ((size_t)b * SEQ + mt * 128) * HDIM;
        size_t bo = ((size_t)b * SEQ + nt * 256) * HDIM;
        Ah = g_qh + ao; Al = g_ql + ao;  lda = HDIM;
        Bh = g_kh + bo; Bl = g_kl + bo;  ldb = HDIM;
        Cf = g_s + (size_t)b * SEQ * SEQ + (size_t)mt * 128 * SEQ + nt * 256;       ldc = SEQ;
    } else { // M_PV
        int mt = blockIdx.x, b = blockIdx.z;
        size_t ao = (size_t)b * SEQ * SEQ + (size_t)mt * 128 * SEQ;
        size_t bo = (size_t)b * EDIM * SEQ;
        Ah = g_ph + ao;  Al = g_pl + ao;   lda = SEQ;
        Bh = g_vth + bo; Bl = g_vtl + bo;  ldb = SEQ;
        Cf = outp + ((size_t)b * SEQ + mt * 128) * EDIM;                            ldc = EDIM;
    }

    float acc[2][8][4];
#pragma unroll
    for (int i = 0; i < 2; i++)
#pragma unroll
        for (int j = 0; j < 8; j++)
#pragma unroll
            for (int e = 0; e < 4; e++) acc[i][j][e] = 0.f;

    // cp.async mapping: A 128 rows x 64B, B 256 rows x 64B, 16B per txn.
    const int r_ld = t >> 2;             // 0..127
    const int cb16 = (t & 3) << 4;       // smem byte within row
    const int cel  = (t & 3) << 3;       // gmem element offset

#define LOAD_STAGE(J, BUF)                                                     \
    {                                                                          \
        const uint32_t sp = sbase + (uint32_t)(BUF) * STAGE_SZ;                \
        uint32_t soA = (uint32_t)(r_ld * ROWB + cb16);                         \
        size_t gaA = (size_t)r_ld * lda + (size_t)(J) * 32 + cel;              \
        CP16(sp + S_AH + soA, Ah + gaA);                                       \
        CP16(sp + S_AL + soA, Al + gaA);                                       \
        _Pragma("unroll")                                                      \
        for (int i = 0; i < 2; i++) {                                          \
            int r = r_ld + 128 * i;                                            \
            uint32_t so = (uint32_t)(r * ROWB + cb16);                         \
            size_t gb = (size_t)r * ldb + (size_t)(J) * 32 + cel;              \
            CP16(sp + S_BH + so, Bh + gb);                                     \
            CP16(sp + S_BL + so, Bl + gb);                                     \
        }                                                                      \
    }

    // ldmatrix offsets (within region)
    const uint32_t aoff = (uint32_t)((wm * 32 + (lane & 15)) * ROWB + ((lane >> 4) << 4));
    const uint32_t boff = (uint32_t)((wn * 64 + ((lane >> 4) << 3) + (lane & 7)) * ROWB
                                     + (((lane >> 3) & 1) << 4));

    // prologue: 2 stages in flight
    LOAD_STAGE(0, 0); CP_COMMIT();
    LOAD_STAGE(1, 1); CP_COMMIT();

#pragma unroll 1
    for (int j = 0; j < NCHUNK; j++) {
        CP_WAIT1();
        __syncthreads();    // single barrier per chunk

        const uint32_t st = sbase + (uint32_t)(j % 3) * STAGE_SZ;
#pragma unroll
        for (int ks = 0; ks < 2; ks++) {
            const uint32_t ko = (uint32_t)(ks * 32);
            uint32_t ah[2][4], al[2][4], b4[4][4];
#pragma unroll
            for (int mf = 0; mf < 2; mf++) {
                uint32_t a = st + aoff + (uint32_t)(mf * 16 * ROWB) + ko;
                ldsm_x4(ah[mf], a + S_AH);
                ldsm_x4(al[mf], a + S_AL);
            }
#pragma unroll
            for (int ng = 0; ng < 4; ng++)
                ldsm_x4(b4[ng], st + S_BH + boff + (uint32_t)(ng * 16 * ROWB) + ko);
#pragma unroll
            for (int mf = 0; mf < 2; mf++)
#pragma unroll
                for (int nf = 0; nf < 8; nf++)
                    mma_bf16(acc[mf][nf], ah[mf], &b4[nf >> 1][(nf & 1) * 2]);
#pragma unroll
            for (int mf = 0; mf < 2; mf++)
#pragma unroll
                for (int nf = 0; nf < 8; nf++)
                    mma_bf16(acc[mf][nf], al[mf], &b4[nf >> 1][(nf & 1) * 2]);
            // reload B regs with lo halves
#pragma unroll
            for (int ng = 0; ng < 4; ng++)
                ldsm_x4(b4[ng], st + S_BL + boff + (uint32_t)(ng * 16 * ROWB) + ko);
#pragma unroll
            for (int mf = 0; mf < 2; mf++)
#pragma unroll
                for (int nf = 0; nf < 8; nf++)
                    mma_bf16(acc[mf][nf], ah[mf], &b4[nf >> 1][(nf & 1) * 2]);

            if (ks == 0) {   // issue next-stage loads between the two k-steps
                if (j + 2 < NCHUNK) LOAD_STAGE(j + 2, (j + 2) % 3);
                CP_COMMIT();
            }
        }
    }

    // ---- epilogue ----
#pragma unroll
    for (int mf = 0; mf < 2; mf++) {
        const int r0 = wm * 32 + mf * 16 + (lane >> 2);
        const int r1 = r0 + 8;
#pragma unroll
        for (int nf = 0; nf < 8; nf++) {
            const int c = wn * 64 + nf * 8 + ((lane & 3) << 1);
            float* a = acc[mf][nf];
            if (MODE == M_PROJQK) {
                float cb0 = bias[c], cb1 = bias[c + 1];
                uint32_t h, l;
                split2(a[0] + cb0, a[1] + cb1, h, l);
                *(uint32_t*)(Ch + (size_t)r0 * ldc + c) = h;
                *(uint32_t*)(Cl + (size_t)r0 * ldc + c) = l;
                split2(a[2] + cb0, a[3] + cb1, h, l);
                *(uint32_t*)(Ch + (size_t)r1 * ldc + c) = h;
                *(uint32_t*)(Cl + (size_t)r1 * ldc + c) = l;
            } else if (MODE == M_PROJVT) {
                float rb0 = bias[r0], rb1 = bias[r1];
                uint32_t h, l;
                split2(a[0] + rb0, a[1] + rb0, h, l);
                *(uint32_t*)(Ch + (size_t)r0 * ldc + c) = h;
                *(uint32_t*)(Cl + (size_t)r0 * ldc + c) = l;
                split2(a[2] + rb1, a[3] + rb1, h, l);
                *(uint32_t*)(Ch + (size_t)r1 * ldc + c) = h;
                *(uint32_t*)(Cl + (size_t)r1 * ldc + c) = l;
            } else {
                *(float2*)(Cf + (size_t)r0 * ldc + c) = make_float2(a[0], a[1]);
                *(float2*)(Cf + (size_t)r1 * ldc + c) = make_float2(a[2], a[3]);
            }
        }
    }
#undef LOAD_STAGE
}

// ---------------------------------------------------------------------------
// Prep: split x into bf16 hi/lo
// ---------------------------------------------------------------------------
__global__ __launch_bounds__(256) void split_x(const float* __restrict__ x)
{
    size_t i = ((size_t)blockIdx.x * 256 + threadIdx.x) * 4;
    float4 v = *(const float4*)(x + i);
    uint32_t h01, l01, h23, l23;
    split2(v.x, v.y, h01, l01);
    split2(v.z, v.w, h23, l23);
    *(uint2*)(g_xh + i) = make_uint2(h01, h23);
    *(uint2*)(g_xl + i) = make_uint2(l01, l23);
}

// ---------------------------------------------------------------------------
// Prep: transpose W and split into bf16 hi/lo
// ---------------------------------------------------------------------------
__global__ __launch_bounds__(256) void transpose_split_w(const float* __restrict__ Wq,
                                                         const float* __restrict__ Wk,
                                                         const float* __restrict__ Wv)
{
    const float* src = (blockIdx.x == 0) ? Wq : (blockIdx.x == 1) ? Wk : Wv;
    __nv_bfloat16* dh = (blockIdx.x == 0) ? g_wqTh : (blockIdx.x == 1) ? g_wkTh : g_wvTh;
    __nv_bfloat16* dl = (blockIdx.x == 0) ? g_wqTl : (blockIdx.x == 1) ? g_wkTl : g_wvTl;
    __shared__ float sm[32 * 33];
    int w = threadIdx.x >> 5, l = threadIdx.x & 31;
    for (int ti = 0; ti < 8; ti++)
        for (int tj = 0; tj < 8; tj++) {
#pragma unroll
            for (int k = 0; k < 4; k++) {
                int r = w * 4 + k;
                sm[r * 33 + l] = src[(size_t)(ti * 32 + r) * 256 + tj * 32 + l];
            }
            __syncthreads();
#pragma unroll
            for (int k = 0; k < 4; k++) {
                int r = w * 4 + k;
                float v = sm[l * 33 + r];
                __nv_bfloat16 h = __float2bfloat16_rn(v);
                float hv = __bfloat162float(h);
                dh[(size_t)(tj * 32 + r) * 256 + ti * 32 + l] = h;
                dl[(size_t)(tj * 32 + r) * 256 + ti * 32 + l] = __float2bfloat16_rn(v - hv);
            }
            __syncthreads();
        }
}

// ---------------------------------------------------------------------------
// Softmax: one warp per row; reads fp32 logits, writes P as bf16 hi/lo
// ---------------------------------------------------------------------------
__global__ __launch_bounds__(256) void softmax_rows()
{
    const size_t row = (size_t)blockIdx.x * 8 + (threadIdx.x >> 5);
    const int l = threadIdx.x & 31;
    const float4* p = (const float4*)(g_s + row * SEQ);

    float4 v[8];
    float mx = -3.4e38f;
#pragma unroll
    for (int i = 0; i < 8; i++) {
        v[i] = p[i * 32 + l];
        mx = fmaxf(mx, fmaxf(fmaxf(v[i].x, v[i].y), fmaxf(v[i].z, v[i].w)));
    }
#pragma unroll
    for (int o = 16; o > 0; o >>= 1) mx = fmaxf(mx, __shfl_xor_sync(0xffffffffu, mx, o));

    float sum = 0.f;
#pragma unroll
    for (int i = 0; i < 8; i++) {
        v[i].x = __expf(v[i].x - mx); v[i].y = __expf(v[i].y - mx);
        v[i].z = __expf(v[i].z - mx); v[i].w = __expf(v[i].w - mx);
        sum += (v[i].x + v[i].y) + (v[i].z + v[i].w);
    }
#pragma unroll
    for (int o = 16; o > 0; o >>= 1) sum += __shfl_xor_sync(0xffffffffu, sum, o);

    const float inv = 1.f / sum;
    __nv_bfloat16* ph = g_ph + row * SEQ;
    __nv_bfloat16* pl = g_pl + row * SEQ;
#pragma unroll
    for (int i = 0; i < 8; i++) {
        uint32_t h01, l01, h23, l23;
        split2(v[i].x * inv, v[i].y * inv, h01, l01);
        split2(v[i].z * inv, v[i].w * inv, h23, l23);
        size_t off = (size_t)(i * 32 + l) * 4;
        *(uint2*)(ph + off) = make_uint2(h01, h23);
        *(uint2*)(pl + off) = make_uint2(l01, l23);
    }
}

// ---------------------------------------------------------------------------
extern "C" void kernel_launch(void* const* d_in, const int* in_sizes, int n_in,
                              void* d_out, int out_size)
{
    const float* x  = (const float*)d_in[0];
    const float* Wq = (const float*)d_in[1];
    const float* bq = (const float*)d_in[2];
    const float* Wk = (const float*)d_in[3];
    const float* bk = (const float*)d_in[4];
    const float* Wv = (const float*)d_in[5];
    const float* bv = (const float*)d_in[6];
    float* out = (float*)d_out;

    cudaFuncSetAttribute(gemm3<M_PROJQK, 8>,  cudaFuncAttributeMaxDynamicSharedMemorySize, SMEM_SZ);
    cudaFuncSetAttribute(gemm3<M_PROJVT, 8>,  cudaFuncAttributeMaxDynamicSharedMemorySize, SMEM_SZ);
    cudaFuncSetAttribute(gemm3<M_QK, 8>,      cudaFuncAttributeMaxDynamicSharedMemorySize, SMEM_SZ);
    cudaFuncSetAttribute(gemm3<M_PV, 32>,     cudaFuncAttributeMaxDynamicSharedMemorySize, SMEM_SZ);

    split_x<<<(MTOT * EDIM) / 1024, 256>>>(x);
    transpose_split_w<<<3, 256>>>(Wq, Wk, Wv);

    gemm3<M_PROJQK, 8><<<dim3(MTOT / 128, 2),    512, SMEM_SZ>>>(bq, bk, bv, out);
    gemm3<M_PROJVT, 8><<<dim3(2, 4, BATCH),      512, SMEM_SZ>>>(bq, bk, bv, out);
    gemm3<M_QK, 8>    <<<dim3(8, 4, BATCH),      512, SMEM_SZ>>>(bq, bk, bv, out);
    softmax_rows      <<<MTOT / 8, 256>>>();
    gemm3<M_PV, 32>   <<<dim3(8, 1, BATCH),      512, SMEM_SZ>>>(bq, bk, bv, out);
}

// round 7
// speedup vs baseline: 1.2100x; 1.1215x over previous
#include <cuda_runtime.h>
#include <cuda_bf16.h>
#include <cuda_fp16.h>
#include <cstdint>

// ---------------------------------------------------------------------------
#define BATCH 64
#define SEQ   1024
#define EDIM  256
#define HDIM  256
#define MTOT  (BATCH * SEQ)       // 65536

// Pre-split operands, produced once, consumed by MMA mainloops.
__device__ __nv_bfloat16 g_xh [(size_t)MTOT * EDIM];
__device__ __nv_bfloat16 g_xl [(size_t)MTOT * EDIM];
__device__ __nv_bfloat16 g_qh [(size_t)MTOT * HDIM];
__device__ __nv_bfloat16 g_ql [(size_t)MTOT * HDIM];
__device__ __nv_bfloat16 g_kh [(size_t)MTOT * HDIM];
__device__ __nv_bfloat16 g_kl [(size_t)MTOT * HDIM];
__device__ __half        g_vth[(size_t)BATCH * EDIM * SEQ];   // V^T fp16 hi
__device__ __half        g_vtl[(size_t)BATCH * EDIM * SEQ];   // V^T fp16 lo
__device__ __half        g_ph [(size_t)BATCH * SEQ * SEQ];    // P fp16 (single)
__device__ float         g_s  [(size_t)BATCH * SEQ * SEQ];    // fp32 logits
__device__ __nv_bfloat16 g_wqTh[EDIM * HDIM], g_wqTl[EDIM * HDIM];
__device__ __nv_bfloat16 g_wkTh[EDIM * HDIM], g_wkTl[EDIM * HDIM];
__device__ __nv_bfloat16 g_wvTh[EDIM * HDIM], g_wvTl[EDIM * HDIM];

// ---------------------------------------------------------------------------
// helpers
// ---------------------------------------------------------------------------
__device__ __forceinline__ uint32_t smem_u32(const void* p) {
    uint32_t a;
    asm("{ .reg .u64 t; cvta.to.shared.u64 t, %1; cvt.u32.u64 %0, t; }" : "=r"(a) : "l"(p));
    return a;
}
__device__ __forceinline__ void ldsm_x4(uint32_t* r, uint32_t addr) {
    asm volatile("ldmatrix.sync.aligned.m8n8.x4.shared.b16 {%0,%1,%2,%3}, [%4];"
                 : "=r"(r[0]), "=r"(r[1]), "=r"(r[2]), "=r"(r[3]) : "r"(addr));
}
__device__ __forceinline__ void mma_bf16(float* c, const uint32_t* a, const uint32_t* b) {
    asm volatile(
        "mma.sync.aligned.m16n8k16.row.col.f32.bf16.bf16.f32 "
        "{%0,%1,%2,%3}, {%4,%5,%6,%7}, {%8,%9}, {%0,%1,%2,%3};"
        : "+f"(c[0]), "+f"(c[1]), "+f"(c[2]), "+f"(c[3])
        : "r"(a[0]), "r"(a[1]), "r"(a[2]), "r"(a[3]), "r"(b[0]), "r"(b[1]));
}
__device__ __forceinline__ void mma_f16(float* c, const uint32_t* a, const uint32_t* b) {
    asm volatile(
        "mma.sync.aligned.m16n8k16.row.col.f32.f16.f16.f32 "
        "{%0,%1,%2,%3}, {%4,%5,%6,%7}, {%8,%9}, {%0,%1,%2,%3};"
        : "+f"(c[0]), "+f"(c[1]), "+f"(c[2]), "+f"(c[3])
        : "r"(a[0]), "r"(a[1]), "r"(a[2]), "r"(a[3]), "r"(b[0]), "r"(b[1]));
}
// hi/lo bf16 split of two floats, packed as bf16x2 words
__device__ __forceinline__ void split2(float x, float y, uint32_t& h, uint32_t& l) {
    __nv_bfloat162 H = __floats2bfloat162_rn(x, y);
    float hx = __bfloat162float(__low2bfloat16(H));
    float hy = __bfloat162float(__high2bfloat16(H));
    __nv_bfloat162 L = __floats2bfloat162_rn(x - hx, y - hy);
    h = *reinterpret_cast<uint32_t*>(&H);
    l = *reinterpret_cast<uint32_t*>(&L);
}
// hi/lo fp16 split of two floats, packed as half2 words
__device__ __forceinline__ void split2h(float x, float y, uint32_t& h, uint32_t& l) {
    __half2 H = __floats2half2_rn(x, y);
    float hx = __half2float(__low2half(H));
    float hy = __half2float(__high2half(H));
    __half2 L = __floats2half2_rn(x - hx, y - hy);
    h = *reinterpret_cast<uint32_t*>(&H);
    l = *reinterpret_cast<uint32_t*>(&L);
}

#define CP16(sm, gp)  asm volatile("cp.async.cg.shared.global [%0], [%1], 16;" :: "r"(sm), "l"(gp))
#define CP_COMMIT()   asm volatile("cp.async.commit_group;" ::: "memory")
#define CP_WAIT1()    asm volatile("cp.async.wait_group 1;" ::: "memory")

// ---------------------------------------------------------------------------
// GEMM: C[128 x 256] = A[128 x K] @ B[256 x K]^T.
// 512 threads, 16 warps (4m x 4n), warp tile 32x64.
// K in chunks of 32; 3-stage cp.async pipeline, ONE __syncthreads per chunk.
// MODE == M_PV: 2-term fp16 (A = P fp16 single; B = V fp16 hi/lo).
// Others: 3-term bf16 (A,B hi/lo).
// ---------------------------------------------------------------------------
#define ROWB   80
#define S_AH   0
#define S_AL   10240                 // 128*80
#define S_BH   20480
#define S_BL   40960                 // + 256*80
#define STAGE_SZ 61440
#define SMEM_SZ  (3 * STAGE_SZ)      // 184320

enum { M_PROJQK = 0, M_PROJVT = 1, M_QK = 2, M_PV = 3 };

template<int MODE, int NCHUNK>
__global__ __launch_bounds__(512, 1)
void gemm3(const float* __restrict__ bq, const float* __restrict__ bk,
           const float* __restrict__ bv, float* __restrict__ outp)
{
    extern __shared__ __align__(128) char smem[];
    const uint32_t sbase = smem_u32(smem);
    const int t    = threadIdx.x;
    const int lane = t & 31;
    const int wid  = t >> 5;          // 0..15
    const int wm   = wid >> 2;        // 0..3  (32-row slab)
    const int wn   = wid & 3;         // 0..3  (64-col slab)

    // ---- operand resolution (raw 16-bit element pointers) ----
    const uint16_t *Ah, *Al = nullptr, *Bh, *Bl;
    __nv_bfloat16 *Ch = nullptr, *Cl = nullptr;
    __half *Chh = nullptr, *Chl = nullptr;
    float* Cf = nullptr;
    const float* bias = nullptr;
    size_t lda, ldb, ldc;

    if (MODE == M_PROJQK) {
        int mt = blockIdx.x, qk = blockIdx.y;
        Ah = (const uint16_t*)(g_xh + (size_t)mt * 128 * EDIM);
        Al = (const uint16_t*)(g_xl + (size_t)mt * 128 * EDIM);                     lda = EDIM;
        Bh = (const uint16_t*)(qk ? g_wkTh : g_wqTh);
        Bl = (const uint16_t*)(qk ? g_wkTl : g_wqTl);                               ldb = EDIM;
        size_t co = (size_t)mt * 128 * HDIM;
        Ch = (qk ? g_kh : g_qh) + co;  Cl = (qk ? g_kl : g_ql) + co;                ldc = HDIM;
        bias = qk ? bk : bq;
    } else if (MODE == M_PROJVT) {
        int mt = blockIdx.x, nt = blockIdx.y, b = blockIdx.z;
        Ah = (const uint16_t*)(g_wvTh + (size_t)mt * 128 * EDIM);
        Al = (const uint16_t*)(g_wvTl + (size_t)mt * 128 * EDIM);                   lda = EDIM;
        size_t bo = ((size_t)b * SEQ + nt * 256) * EDIM;
        Bh = (const uint16_t*)(g_xh + bo);  Bl = (const uint16_t*)(g_xl + bo);      ldb = EDIM;
        size_t co = (size_t)b * EDIM * SEQ + (size_t)mt * 128 * SEQ + nt * 256;
        Chh = g_vth + co;  Chl = g_vtl + co;                                        ldc = SEQ;
        bias = bv + mt * 128;
    } else if (MODE == M_QK) {
        int mt = blockIdx.x, nt = blockIdx.y, b = blockIdx.z;
        size_t ao = ((size_t)b * SEQ + mt * 128) * HDIM;
        size_t bo = ((size_t)b * SEQ + nt * 256) * HDIM;
        Ah = (const uint16_t*)(g_qh + ao); Al = (const uint16_t*)(g_ql + ao);       lda = HDIM;
        Bh = (const uint16_t*)(g_kh + bo); Bl = (const uint16_t*)(g_kl + bo);       ldb = HDIM;
        Cf = g_s + (size_t)b * SEQ * SEQ + (size_t)mt * 128 * SEQ + nt * 256;       ldc = SEQ;
    } else { // M_PV: A = P fp16 (single), B = V^T fp16 hi/lo
        int mt = blockIdx.x, b = blockIdx.z;
        Ah = (const uint16_t*)(g_ph + (size_t)b * SEQ * SEQ + (size_t)mt * 128 * SEQ); lda = SEQ;
        size_t bo = (size_t)b * EDIM * SEQ;
        Bh = (const uint16_t*)(g_vth + bo); Bl = (const uint16_t*)(g_vtl + bo);     ldb = SEQ;
        Cf = outp + ((size_t)b * SEQ + mt * 128) * EDIM;                            ldc = EDIM;
    }

    float acc[2][8][4];
#pragma unroll
    for (int i = 0; i < 2; i++)
#pragma unroll
        for (int j = 0; j < 8; j++)
#pragma unroll
            for (int e = 0; e < 4; e++) acc[i][j][e] = 0.f;

    // cp.async mapping: A 128 rows x 64B, B 256 rows x 64B, 16B per txn.
    const int r_ld = t >> 2;             // 0..127
    const int cb16 = (t & 3) << 4;       // smem byte within row
    const int cel  = (t & 3) << 3;       // gmem element offset

#define LOAD_STAGE(J, BUF)                                                     \
    {                                                                          \
        const uint32_t sp = sbase + (uint32_t)(BUF) * STAGE_SZ;                \
        uint32_t soA = (uint32_t)(r_ld * ROWB + cb16);                         \
        size_t gaA = (size_t)r_ld * lda + (size_t)(J) * 32 + cel;              \
        CP16(sp + S_AH + soA, Ah + gaA);                                       \
        if (MODE != M_PV) CP16(sp + S_AL + soA, Al + gaA);                     \
        _Pragma("unroll")                                                      \
        for (int i = 0; i < 2; i++) {                                          \
            int r = r_ld + 128 * i;                                            \
            uint32_t so = (uint32_t)(r * ROWB + cb16);                         \
            size_t gb = (size_t)r * ldb + (size_t)(J) * 32 + cel;              \
            CP16(sp + S_BH + so, Bh + gb);                                     \
            CP16(sp + S_BL + so, Bl + gb);                                     \
        }                                                                      \
    }

    // ldmatrix offsets (within region)
    const uint32_t aoff = (uint32_t)((wm * 32 + (lane & 15)) * ROWB + ((lane >> 4) << 4));
    const uint32_t boff = (uint32_t)((wn * 64 + ((lane >> 4) << 3) + (lane & 7)) * ROWB
                                     + (((lane >> 3) & 1) << 4));

    // prologue: 2 stages in flight
    LOAD_STAGE(0, 0); CP_COMMIT();
    LOAD_STAGE(1, 1); CP_COMMIT();

#pragma unroll 1
    for (int j = 0; j < NCHUNK; j++) {
        CP_WAIT1();
        __syncthreads();    // single barrier per chunk

        const uint32_t st = sbase + (uint32_t)(j % 3) * STAGE_SZ;
#pragma unroll
        for (int ks = 0; ks < 2; ks++) {
            const uint32_t ko = (uint32_t)(ks * 32);
            uint32_t ah[2][4], al[2][4], b4[4][4];
#pragma unroll
            for (int mf = 0; mf < 2; mf++) {
                uint32_t a = st + aoff + (uint32_t)(mf * 16 * ROWB) + ko;
                ldsm_x4(ah[mf], a + S_AH);
                if (MODE != M_PV) ldsm_x4(al[mf], a + S_AL);
            }
#pragma unroll
            for (int ng = 0; ng < 4; ng++)
                ldsm_x4(b4[ng], st + S_BH + boff + (uint32_t)(ng * 16 * ROWB) + ko);
            if (MODE == M_PV) {
#pragma unroll
                for (int mf = 0; mf < 2; mf++)
#pragma unroll
                    for (int nf = 0; nf < 8; nf++)
                        mma_f16(acc[mf][nf], ah[mf], &b4[nf >> 1][(nf & 1) * 2]);
#pragma unroll
                for (int ng = 0; ng < 4; ng++)
                    ldsm_x4(b4[ng], st + S_BL + boff + (uint32_t)(ng * 16 * ROWB) + ko);
#pragma unroll
                for (int mf = 0; mf < 2; mf++)
#pragma unroll
                    for (int nf = 0; nf < 8; nf++)
                        mma_f16(acc[mf][nf], ah[mf], &b4[nf >> 1][(nf & 1) * 2]);
            } else {
#pragma unroll
                for (int mf = 0; mf < 2; mf++)
#pragma unroll
                    for (int nf = 0; nf < 8; nf++)
                        mma_bf16(acc[mf][nf], ah[mf], &b4[nf >> 1][(nf & 1) * 2]);
#pragma unroll
                for (int mf = 0; mf < 2; mf++)
#pragma unroll
                    for (int nf = 0; nf < 8; nf++)
                        mma_bf16(acc[mf][nf], al[mf], &b4[nf >> 1][(nf & 1) * 2]);
                // reload B regs with lo halves
#pragma unroll
                for (int ng = 0; ng < 4; ng++)
                    ldsm_x4(b4[ng], st + S_BL + boff + (uint32_t)(ng * 16 * ROWB) + ko);
#pragma unroll
                for (int mf = 0; mf < 2; mf++)
#pragma unroll
                    for (int nf = 0; nf < 8; nf++)
                        mma_bf16(acc[mf][nf], ah[mf], &b4[nf >> 1][(nf & 1) * 2]);
            }

            if (ks == 0) {   // issue next-stage loads between the two k-steps
                if (j + 2 < NCHUNK) LOAD_STAGE(j + 2, (j + 2) % 3);
                CP_COMMIT();
            }
        }
    }

    // ---- epilogue ----
#pragma unroll
    for (int mf = 0; mf < 2; mf++) {
        const int r0 = wm * 32 + mf * 16 + (lane >> 2);
        const int r1 = r0 + 8;
#pragma unroll
        for (int nf = 0; nf < 8; nf++) {
            const int c = wn * 64 + nf * 8 + ((lane & 3) << 1);
            float* a = acc[mf][nf];
            if (MODE == M_PROJQK) {
                float cb0 = bias[c], cb1 = bias[c + 1];
                uint32_t h, l;
                split2(a[0] + cb0, a[1] + cb1, h, l);
                *(uint32_t*)(Ch + (size_t)r0 * ldc + c) = h;
                *(uint32_t*)(Cl + (size_t)r0 * ldc + c) = l;
                split2(a[2] + cb0, a[3] + cb1, h, l);
                *(uint32_t*)(Ch + (size_t)r1 * ldc + c) = h;
                *(uint32_t*)(Cl + (size_t)r1 * ldc + c) = l;
            } else if (MODE == M_PROJVT) {
                float rb0 = bias[r0], rb1 = bias[r1];
                uint32_t h, l;
                split2h(a[0] + rb0, a[1] + rb0, h, l);
                *(uint32_t*)(Chh + (size_t)r0 * ldc + c) = h;
                *(uint32_t*)(Chl + (size_t)r0 * ldc + c) = l;
                split2h(a[2] + rb1, a[3] + rb1, h, l);
                *(uint32_t*)(Chh + (size_t)r1 * ldc + c) = h;
                *(uint32_t*)(Chl + (size_t)r1 * ldc + c) = l;
            } else {
                *(float2*)(Cf + (size_t)r0 * ldc + c) = make_float2(a[0], a[1]);
                *(float2*)(Cf + (size_t)r1 * ldc + c) = make_float2(a[2], a[3]);
            }
        }
    }
#undef LOAD_STAGE
}

// ---------------------------------------------------------------------------
// Prep: split x into bf16 hi/lo
// ---------------------------------------------------------------------------
__global__ __launch_bounds__(256) void split_x(const float* __restrict__ x)
{
    size_t i = ((size_t)blockIdx.x * 256 + threadIdx.x) * 4;
    float4 v = *(const float4*)(x + i);
    uint32_t h01, l01, h23, l23;
    split2(v.x, v.y, h01, l01);
    split2(v.z, v.w, h23, l23);
    *(uint2*)(g_xh + i) = make_uint2(h01, h23);
    *(uint2*)(g_xl + i) = make_uint2(l01, l23);
}

// ---------------------------------------------------------------------------
// Prep: transpose W and split into bf16 hi/lo
// ---------------------------------------------------------------------------
__global__ __launch_bounds__(256) void transpose_split_w(const float* __restrict__ Wq,
                                                         const float* __restrict__ Wk,
                                                         const float* __restrict__ Wv)
{
    const float* src = (blockIdx.x == 0) ? Wq : (blockIdx.x == 1) ? Wk : Wv;
    __nv_bfloat16* dh = (blockIdx.x == 0) ? g_wqTh : (blockIdx.x == 1) ? g_wkTh : g_wvTh;
    __nv_bfloat16* dl = (blockIdx.x == 0) ? g_wqTl : (blockIdx.x == 1) ? g_wkTl : g_wvTl;
    __shared__ float sm[32 * 33];
    int w = threadIdx.x >> 5, l = threadIdx.x & 31;
    for (int ti = 0; ti < 8; ti++)
        for (int tj = 0; tj < 8; tj++) {
#pragma unroll
            for (int k = 0; k < 4; k++) {
                int r = w * 4 + k;
                sm[r * 33 + l] = src[(size_t)(ti * 32 + r) * 256 + tj * 32 + l];
            }
            __syncthreads();
#pragma unroll
            for (int k = 0; k < 4; k++) {
                int r = w * 4 + k;
                float v = sm[l * 33 + r];
                __nv_bfloat16 h = __float2bfloat16_rn(v);
                float hv = __bfloat162float(h);
                dh[(size_t)(tj * 32 + r) * 256 + ti * 32 + l] = h;
                dl[(size_t)(tj * 32 + r) * 256 + ti * 32 + l] = __float2bfloat16_rn(v - hv);
            }
            __syncthreads();
        }
}

// ---------------------------------------------------------------------------
// Softmax: one warp per row; reads fp32 logits, writes P as fp16 (single)
// ---------------------------------------------------------------------------
__global__ __launch_bounds__(256) void softmax_rows()
{
    const size_t row = (size_t)blockIdx.x * 8 + (threadIdx.x >> 5);
    const int l = threadIdx.x & 31;
    const float4* p = (const float4*)(g_s + row * SEQ);

    float4 v[8];
    float mx = -3.4e38f;
#pragma unroll
    for (int i = 0; i < 8; i++) {
        v[i] = p[i * 32 + l];
        mx = fmaxf(mx, fmaxf(fmaxf(v[i].x, v[i].y), fmaxf(v[i].z, v[i].w)));
    }
#pragma unroll
    for (int o = 16; o > 0; o >>= 1) mx = fmaxf(mx, __shfl_xor_sync(0xffffffffu, mx, o));

    float sum = 0.f;
#pragma unroll
    for (int i = 0; i < 8; i++) {
        v[i].x = __expf(v[i].x - mx); v[i].y = __expf(v[i].y - mx);
        v[i].z = __expf(v[i].z - mx); v[i].w = __expf(v[i].w - mx);
        sum += (v[i].x + v[i].y) + (v[i].z + v[i].w);
    }
#pragma unroll
    for (int o = 16; o > 0; o >>= 1) sum += __shfl_xor_sync(0xffffffffu, sum, o);

    const float inv = 1.f / sum;
    __half* ph = g_ph + row * SEQ;
#pragma unroll
    for (int i = 0; i < 8; i++) {
        __half2 a = __floats2half2_rn(v[i].x * inv, v[i].y * inv);
        __half2 b = __floats2half2_rn(v[i].z * inv, v[i].w * inv);
        uint2 w;
        w.x = *reinterpret_cast<uint32_t*>(&a);
        w.y = *reinterpret_cast<uint32_t*>(&b);
        *(uint2*)(ph + (size_t)(i * 32 + l) * 4) = w;
    }
}

// ---------------------------------------------------------------------------
extern "C" void kernel_launch(void* const* d_in, const int* in_sizes, int n_in,
                              void* d_out, int out_size)
{
    const float* x  = (const float*)d_in[0];
    const float* Wq = (const float*)d_in[1];
    const float* bq = (const float*)d_in[2];
    const float* Wk = (const float*)d_in[3];
    const float* bk = (const float*)d_in[4];
    const float* Wv = (const float*)d_in[5];
    const float* bv = (const float*)d_in[6];
    float* out = (float*)d_out;

    cudaFuncSetAttribute(gemm3<M_PROJQK, 8>,  cudaFuncAttributeMaxDynamicSharedMemorySize, SMEM_SZ);
    cudaFuncSetAttribute(gemm3<M_PROJVT, 8>,  cudaFuncAttributeMaxDynamicSharedMemorySize, SMEM_SZ);
    cudaFuncSetAttribute(gemm3<M_QK, 8>,      cudaFuncAttributeMaxDynamicSharedMemorySize, SMEM_SZ);
    cudaFuncSetAttribute(gemm3<M_PV, 32>,     cudaFuncAttributeMaxDynamicSharedMemorySize, SMEM_SZ);

    split_x<<<(MTOT * EDIM) / 1024, 256>>>(x);
    transpose_split_w<<<3, 256>>>(Wq, Wk, Wv);

    gemm3<M_PROJQK, 8><<<dim3(MTOT / 128, 2),    512, SMEM_SZ>>>(bq, bk, bv, out);
    gemm3<M_PROJVT, 8><<<dim3(2, 4, BATCH),      512, SMEM_SZ>>>(bq, bk, bv, out);
    gemm3<M_QK, 8>    <<<dim3(8, 4, BATCH),      512, SMEM_SZ>>>(bq, bk, bv, out);
    softmax_rows      <<<MTOT / 8, 256>>>();
    gemm3<M_PV, 32>   <<<dim3(8, 1, BATCH),      512, SMEM_SZ>>>(bq, bk, bv, out);
}